// round 10
// baseline (speedup 1.0000x reference)
#include <cuda_runtime.h>
#include <cstdint>

// ---------------------------------------------------------------------------
// Problem constants
// ---------------------------------------------------------------------------
#define KK 16
#define YY 32
#define CC 16
#define NBUCKET (KK * YY)          // 512
#define ACC_ELEMS (NBUCKET * CC)   // 8192
#define ACC_F4 (ACC_ELEMS / 4)     // 2048 float4 per replica
#define KSLICE_F4 (ACC_F4 / KK)    // 128 float4 per (replica, k)
#define NREP 32                    // accumulator replicas
#define EPS_F 1e-8f

#define SGRID 1184                 // 148 SMs x 8 CTAs x 256 thr = exact full residency
#define TPB 256

// Replicated scratch: 32 x 8192 f32 = 1 MB. Zero-initialized at module load;
// cc_finalize resets it after reading, so every subsequent launch (and every
// graph replay) enters with it zeroed. 16B-aligned for red.v4 / float4.
__device__ __align__(16) float g_acc[NREP * ACC_ELEMS];

// ---------------------------------------------------------------------------
// Kernel 1: scatter-add (body UNCHANGED — measured ~70us; protect it).
// One thread per float4 (quarter-row), coalesced 16B loads, red.global.add.v4
// into this CTA's replica. PDL trigger at exit lets finalize launch early.
// ---------------------------------------------------------------------------
__global__ void __launch_bounds__(TPB)
cc_scatter(const int* __restrict__ xl,
           const int* __restrict__ yl,
           const float4* __restrict__ post,
           int n_f4) {
    int stride = gridDim.x * blockDim.x;
    float* rep = &g_acc[(blockIdx.x & (NREP - 1)) * ACC_ELEMS];
    for (int i = blockIdx.x * blockDim.x + threadIdx.x; i < n_f4; i += stride) {
        int row = i >> 2;
        int c4  = i & 3;
        float4 v = post[i];
        int b = xl[row] * YY + yl[row];              // bucket in [0,512)
        float* dst = &rep[b * CC + c4 * 4];
        asm volatile("red.global.add.v4.f32 [%0], {%1, %2, %3, %4};"
                     :: "l"(dst), "f"(v.x), "f"(v.y), "f"(v.z), "f"(v.w)
                     : "memory");
    }
    cudaTriggerProgrammaticLaunchCompletion();
}

// ---------------------------------------------------------------------------
// Kernel 2: finalize — vectorized parallel epilogue. 16 blocks (one per k),
// 512 threads. Thread (quad = tid>>7, s = tid&127):
//   - partial = sum of float4 slot s over replicas quad*8 .. quad*8+7
//   - quad partials combined via smem; +eps; normalize over Y; write out
//   - resets exactly the (replica, slot) f4s it read (disjoint -> race-free)
// ---------------------------------------------------------------------------
__global__ void __launch_bounds__(512)
cc_finalize(float* __restrict__ out) {
    __shared__ __align__(16) float4 s_part[4][KSLICE_F4];  // 8 KB
    __shared__ float s_val[YY * CC];                       // 2 KB numerators
    __shared__ float s_inv[CC];

    cudaGridDependencySynchronize();   // PDL: wait for full scatter grid

    int k    = blockIdx.x;             // 0..15
    int tid  = threadIdx.x;            // 0..511
    int quad = tid >> 7;               // 0..3  (replica group of 8)
    int s    = tid & 127;              // f4 slot within this k-slice

    const float4* accv = (const float4*)g_acc;
    int base = k * KSLICE_F4 + s;

    // 8 independent LDG.128 per thread
    float4 a = make_float4(0.f, 0.f, 0.f, 0.f);
#pragma unroll
    for (int j = 0; j < 8; j++) {
        float4 v = accv[(quad * 8 + j) * ACC_F4 + base];
        a.x += v.x; a.y += v.y; a.z += v.z; a.w += v.w;
    }
    s_part[quad][s] = a;
    __syncthreads();

    // combine quads (threads 0..127), add eps, publish scalar numerators
    if (tid < KSLICE_F4) {
        float4 q0 = s_part[0][tid], q1 = s_part[1][tid];
        float4 q2 = s_part[2][tid], q3 = s_part[3][tid];
        s_val[tid * 4 + 0] = q0.x + q1.x + q2.x + q3.x + EPS_F;
        s_val[tid * 4 + 1] = q0.y + q1.y + q2.y + q3.y + EPS_F;
        s_val[tid * 4 + 2] = q0.z + q1.z + q2.z + q3.z + EPS_F;
        s_val[tid * 4 + 3] = q0.w + q1.w + q2.w + q3.w + EPS_F;
    }
    __syncthreads();

    // denominator per channel: sum over Y
    if (tid < CC) {
        float d = 0.0f;
#pragma unroll
        for (int y = 0; y < YY; y++)
            d += s_val[y * CC + tid];
        s_inv[tid] = 1.0f / d;
    }
    __syncthreads();

    // write normalized output (one elem per thread)
    out[k * (YY * CC) + tid] = s_val[tid] * s_inv[tid & 15];

    // reset exactly what this thread read (8 STG.128)
    float4* waccv = (float4*)g_acc;
    float4 z = make_float4(0.f, 0.f, 0.f, 0.f);
#pragma unroll
    for (int j = 0; j < 8; j++)
        waccv[(quad * 8 + j) * ACC_F4 + base] = z;
}

// ---------------------------------------------------------------------------
// Launch
// ---------------------------------------------------------------------------
extern "C" void kernel_launch(void* const* d_in, const int* in_sizes, int n_in,
                              void* d_out, int out_size) {
    const int*    xl   = (const int*)d_in[0];        // x_labels [N] int32
    const int*    yl   = (const int*)d_in[1];        // y_labels [N] int32
    const float4* post = (const float4*)d_in[2];     // posterior [N,16] f32
    float* out = (float*)d_out;                      // [16,32,16] f32

    int n = in_sizes[0];
    int n_f4 = n * (CC / 4);

    cc_scatter<<<SGRID, TPB>>>(xl, yl, post, n_f4);

    // finalize with programmatic dependent launch (overlaps launch with
    // scatter tail; gridDependencySynchronize orders the data).
    cudaLaunchConfig_t cfg = {};
    cfg.gridDim = dim3(KK);
    cfg.blockDim = dim3(512);
    cfg.dynamicSmemBytes = 0;
    cfg.stream = 0;
    cudaLaunchAttribute attr[1];
    attr[0].id = cudaLaunchAttributeProgrammaticStreamSerialization;
    attr[0].val.programmaticStreamSerializationAllowed = 1;
    cfg.attrs = attr;
    cfg.numAttrs = 1;
    cudaError_t e = cudaLaunchKernelEx(&cfg, cc_finalize, (float*)d_out);
    if (e != cudaSuccess) {
        // PDL unsupported -> plain launch (still correct, just serialized)
        cc_finalize<<<KK, 512>>>(out);
    }
}